// round 2
// baseline (speedup 1.0000x reference)
#include <cuda_runtime.h>
#include <math.h>

#define B_ 4
#define L_ 8192
#define D_ 2048
#define H_ 32
#define HD_ 64
#define CHUNK_ 256
#define TS_ 257          // smem tile token stride (floats): bank = (d + tok) mod 32

// per-(token,head) softmax denominators, combined in kernel 2
__device__ float g_denoms[B_ * L_ * H_];

// Load one 256-token chunk's head-slice into transposed smem tile [64][257].
__device__ __forceinline__ void load_tile(const float* __restrict__ xh,
                                          int base_tok, float* __restrict__ tile,
                                          int tid) {
    // 256 tokens * 16 float4 = 4096 vector loads, 16 per thread, coalesced in gmem
    #pragma unroll
    for (int it = 0; it < 16; it++) {
        const int idx = tid + it * 256;
        const int tok = idx >> 4;            // 16 float4 per token
        const int c4  = (idx & 15) << 2;     // dim base
        const float4 v = *reinterpret_cast<const float4*>(
            xh + (size_t)(base_tok + tok) * D_ + c4);
        tile[(c4 + 0) * TS_ + tok] = v.x;
        tile[(c4 + 1) * TS_ + tok] = v.y;
        tile[(c4 + 2) * TS_ + tok] = v.z;
        tile[(c4 + 3) * TS_ + tok] = v.w;
    }
}

__global__ __launch_bounds__(256, 1)
void dda_attn_kernel(const float* __restrict__ x, float* __restrict__ out) {
    const int chunk  = blockIdx.x;           // 0..31   (256-token chunk)
    const int h      = blockIdx.y;           // 0..31
    const int b      = blockIdx.z;           // 0..3
    const int tid    = threadIdx.x;          // 0..255, one query per thread
    const int t_loc  = tid;
    const int t_glob = chunk * CHUNK_ + t_loc;
    const float scale = 0.125f;              // 1/sqrt(64)

    extern __shared__ float tile[];          // [HD_][TS_]

    const float* xh = x + (size_t)b * L_ * D_ + h * HD_;

    // query vector in registers
    float q[HD_];
    {
        const float* qp = xh + (size_t)t_glob * D_;
        #pragma unroll
        for (int i = 0; i < HD_ / 4; i++) {
            const float4 v = *reinterpret_cast<const float4*>(qp + 4 * i);
            q[4*i+0] = v.x; q[4*i+1] = v.y; q[4*i+2] = v.z; q[4*i+3] = v.w;
        }
    }

    float acc[HD_];
    #pragma unroll
    for (int d = 0; d < HD_; d++) acc[d] = 0.f;

    // ------------- rate 5 (m=32): online softmax over the 4 chunks of the
    // ------------- enclosing 1024-window; iterate so OWN chunk lands last.
    float m_run = -INFINITY, l_run = 0.f;
    const int o32     = t_glob & 31;
    const int wchunk0 = chunk & ~3;
    const int myc     = chunk & 3;

    for (int cc = 1; cc <= 4; cc++) {
        const int c = wchunk0 + ((myc + cc) & 3);
        __syncthreads();
        load_tile(xh, c * CHUNK_, tile, tid);
        __syncthreads();

        float s[8];
        #pragma unroll
        for (int j = 0; j < 8; j++) {
            const int tok = o32 + 32 * j;    // lanes -> distinct tok mod 32: conflict-free
            float a0 = 0.f, a1 = 0.f, a2 = 0.f, a3 = 0.f;
            #pragma unroll
            for (int d = 0; d < HD_; d += 4) {
                a0 = fmaf(tile[(d+0)*TS_ + tok], q[d+0], a0);
                a1 = fmaf(tile[(d+1)*TS_ + tok], q[d+1], a1);
                a2 = fmaf(tile[(d+2)*TS_ + tok], q[d+2], a2);
                a3 = fmaf(tile[(d+3)*TS_ + tok], q[d+3], a3);
            }
            s[j] = ((a0 + a1) + (a2 + a3)) * scale;
        }
        float mx = m_run;
        #pragma unroll
        for (int j = 0; j < 8; j++) mx = fmaxf(mx, s[j]);
        const float alpha = __expf(m_run - mx);     // first iter: exp(-inf)=0
        float p[8];
        float ls = 0.f;
        #pragma unroll
        for (int j = 0; j < 8; j++) { p[j] = __expf(s[j] - mx); ls += p[j]; }
        l_run = l_run * alpha + ls;
        m_run = mx;
        #pragma unroll
        for (int d = 0; d < HD_; d++) acc[d] *= alpha;
        #pragma unroll
        for (int j = 0; j < 8; j++) {
            const int tok = o32 + 32 * j;
            const float pj = p[j];
            #pragma unroll
            for (int d = 0; d < HD_; d++)
                acc[d] = fmaf(pj, tile[d * TS_ + tok], acc[d]);
        }
    }
    float den = l_run * __expf(m_run);              // = sum_k exp(s_k), stable
    {
        const float inv = 1.f / l_run;
        #pragma unroll
        for (int d = 0; d < HD_; d++) acc[d] *= inv;
    }

    // ------------- rates 4..1: all local to own chunk (now resident in tile)
    #pragma unroll
    for (int i = 4; i >= 1; i--) {
        const int m = 1 << i;
        const int w = m * m;                         // aligned window size
        const int base = t_loc & ~(w - 1);
        const int o    = t_loc & (m - 1);
        float s[16];
        float mx = -INFINITY;
        #pragma unroll
        for (int j = 0; j < m; j++) {
            const int tok = base + o + m * j;
            float a0 = 0.f, a1 = 0.f, a2 = 0.f, a3 = 0.f;
            #pragma unroll
            for (int d = 0; d < HD_; d += 4) {
                a0 = fmaf(tile[(d+0)*TS_ + tok], q[d+0], a0);
                a1 = fmaf(tile[(d+1)*TS_ + tok], q[d+1], a1);
                a2 = fmaf(tile[(d+2)*TS_ + tok], q[d+2], a2);
                a3 = fmaf(tile[(d+3)*TS_ + tok], q[d+3], a3);
            }
            s[j] = ((a0 + a1) + (a2 + a3)) * scale;
            mx = fmaxf(mx, s[j]);
        }
        float sum = 0.f;
        #pragma unroll
        for (int j = 0; j < m; j++) { s[j] = __expf(s[j] - mx); sum += s[j]; }
        den += sum * __expf(mx);
        const float inv = 1.f / sum;
        #pragma unroll
        for (int j = 0; j < m; j++) {
            const int tok = base + o + m * j;
            const float pj = s[j] * inv;
            #pragma unroll
            for (int d = 0; d < HD_; d++)
                acc[d] = fmaf(pj, tile[d * TS_ + tok], acc[d]);
        }
    }

    // ------------- rate 0: self-attention over a single key (prob = 1)
    {
        float a0 = 0.f, a1 = 0.f, a2 = 0.f, a3 = 0.f;
        #pragma unroll
        for (int d = 0; d < HD_; d += 4) {
            a0 = fmaf(q[d+0], q[d+0], a0);
            a1 = fmaf(q[d+1], q[d+1], a1);
            a2 = fmaf(q[d+2], q[d+2], a2);
            a3 = fmaf(q[d+3], q[d+3], a3);
        }
        den += __expf(((a0 + a1) + (a2 + a3)) * scale);
        #pragma unroll
        for (int d = 0; d < HD_; d++) acc[d] += q[d];
    }

    g_denoms[((size_t)b * L_ + t_glob) * H_ + h] = den;
    float* op = out + (size_t)b * L_ * D_ + (size_t)t_glob * D_ + h * HD_;
    #pragma unroll
    for (int i = 0; i < HD_ / 4; i++) {
        const float4 v = make_float4(acc[4*i+0], acc[4*i+1], acc[4*i+2], acc[4*i+3]);
        *reinterpret_cast<float4*>(op + 4 * i) = v;
    }
}

// Per-token: w = softmax over heads of denoms; scale each head slice of out.
__global__ __launch_bounds__(256, 4)
void dda_combine_kernel(float* __restrict__ out) {
    const int token = blockIdx.x;                    // 0..B*L-1
    __shared__ float wsh[H_];
    const int tid = threadIdx.x;
    if (tid < 32) {
        const float v = g_denoms[(size_t)token * H_ + tid];
        float mx = v;
        #pragma unroll
        for (int off = 16; off > 0; off >>= 1)
            mx = fmaxf(mx, __shfl_xor_sync(0xffffffffu, mx, off));
        const float e = __expf(v - mx);
        float sum = e;
        #pragma unroll
        for (int off = 16; off > 0; off >>= 1)
            sum += __shfl_xor_sync(0xffffffffu, sum, off);
        wsh[tid] = e / sum;
    }
    __syncthreads();
    float4* p = reinterpret_cast<float4*>(out + (size_t)token * D_);
    #pragma unroll
    for (int it = 0; it < (D_ / 4) / 256; it++) {    // 2 float4 per thread
        const int i = tid + it * 256;
        const float ww = wsh[i >> 4];                // 16 float4 per head
        float4 v = p[i];
        v.x *= ww; v.y *= ww; v.z *= ww; v.w *= ww;
        p[i] = v;
    }
}

extern "C" void kernel_launch(void* const* d_in, const int* in_sizes, int n_in,
                              void* d_out, int out_size) {
    const float* x = (const float*)d_in[0];
    float* out = (float*)d_out;

    const int smem_bytes = HD_ * TS_ * (int)sizeof(float);   // 65792 B
    cudaFuncSetAttribute(dda_attn_kernel,
                         cudaFuncAttributeMaxDynamicSharedMemorySize, smem_bytes);

    dim3 grid(L_ / CHUNK_, H_, B_);                  // 32 x 32 x 4 = 4096 CTAs
    dda_attn_kernel<<<grid, 256, smem_bytes>>>(x, out);
    dda_combine_kernel<<<B_ * L_, 256>>>(out);
}